// round 9
// baseline (speedup 1.0000x reference)
#include <cuda_runtime.h>
#include <math.h>

// SpatialPositionalEncoding2D: out[b,l,d] = x[b,l,d] + pe(l,d)
// h = w = 128, L = 16384, D = 256, dh = 128, b = 8.
//
// Final micro-variant: 256-bit global loads AND stores (ld/st.global.v8.b32,
// sm_100+). Same batch-8 amortized streaming as the 36.1us best, but half the
// LDG/STG instruction count and L1tex wavefront pressure per byte. Loads use
// non-volatile asm so ptxas can batch them (R5's asm volatile killed MLP).

namespace {
constexpr int H  = 128;
constexpr int W  = 128;
constexpr int L  = H * W;       // 16384
constexpr int D  = 256;
constexpr int D4 = D / 4;       // 64 float4 per position
constexpr unsigned STRIDE4 = (unsigned)L * D4;   // float4 per batch image
constexpr int OCTS = D / 8;     // 32 octs (8 floats) per position
constexpr int POS_PER_BLOCK = 8;   // 256 threads = 8 positions x 32 octs
}

struct f8 { float4 a, b; };

__device__ __forceinline__ f8 ld8(const float4* p) {
    f8 v;
    // Non-volatile: compiler may hoist/batch these freely (addresses distinct).
    asm("ld.global.v8.f32 {%0,%1,%2,%3,%4,%5,%6,%7}, [%8];"
        : "=f"(v.a.x), "=f"(v.a.y), "=f"(v.a.z), "=f"(v.a.w),
          "=f"(v.b.x), "=f"(v.b.y), "=f"(v.b.z), "=f"(v.b.w)
        : "l"(p));
    return v;
}

__device__ __forceinline__ void st8(float4* p, const f8& v) {
    asm volatile("st.global.v8.f32 [%0], {%1,%2,%3,%4,%5,%6,%7,%8};"
                 :: "l"(p),
                    "f"(v.a.x), "f"(v.a.y), "f"(v.a.z), "f"(v.a.w),
                    "f"(v.b.x), "f"(v.b.y), "f"(v.b.z), "f"(v.b.w)
                 : "memory");
}

__global__ void __launch_bounds__(256, 4)
pe_add_kernel(const float4* __restrict__ x, float4* __restrict__ out, int b)
{
    const int tid = threadIdx.x;
    const int oct = tid & (OCTS - 1);                        // 0..31
    const int l   = (blockIdx.x << 3) + (tid >> 5);          // position
    const int d0  = oct << 3;                                // first channel

    const int row = l >> 7;        // l / 128
    const int col = l & (W - 1);   // l % 128

    // All 8 channels of this oct sit in one half (8 divides 128).
    const bool rhalf = (d0 < 128);
    const float pos  = rhalf ? (float)row : (float)col;
    const int   j0   = rhalf ? (d0 >> 1) : ((d0 - 128) >> 1);

    // freq[j] = exp(j * (-2*ln(10000)/128)); channels interleave sin/cos.
    const float KF = -0.14391156831212787f;
    float pef[8];
    #pragma unroll
    for (int k = 0; k < 4; k++) {
        const float f = expf((float)(j0 + k) * KF);
        sincosf(pos * f, &pef[2 * k], &pef[2 * k + 1]);
    }

    const unsigned base = (unsigned)l * D4 + (unsigned)(oct << 1); // 32B units/2

    if (b == 8) {
        // Two groups of 4 batches in flight (32 data regs per group).
        #pragma unroll
        for (int g = 0; g < 2; g++) {
            f8 v[4];
            #pragma unroll
            for (int i = 0; i < 4; i++)
                v[i] = ld8(x + base + (unsigned)(g * 4 + i) * STRIDE4);
            #pragma unroll
            for (int i = 0; i < 4; i++) {
                v[i].a.x += pef[0]; v[i].a.y += pef[1];
                v[i].a.z += pef[2]; v[i].a.w += pef[3];
                v[i].b.x += pef[4]; v[i].b.y += pef[5];
                v[i].b.z += pef[6]; v[i].b.w += pef[7];
                st8(out + base + (unsigned)(g * 4 + i) * STRIDE4, v[i]);
            }
        }
    } else {
        for (int bi = 0; bi < b; bi++) {
            f8 v = ld8(x + base + (unsigned)bi * STRIDE4);
            v.a.x += pef[0]; v.a.y += pef[1]; v.a.z += pef[2]; v.a.w += pef[3];
            v.b.x += pef[4]; v.b.y += pef[5]; v.b.z += pef[6]; v.b.w += pef[7];
            st8(out + base + (unsigned)bi * STRIDE4, v);
        }
    }
}

extern "C" void kernel_launch(void* const* d_in, const int* in_sizes, int n_in,
                              void* d_out, int out_size)
{
    const float4* x  = (const float4*)d_in[0];
    float4* out      = (float4*)d_out;
    const int n      = in_sizes[0];          // total elements of x
    const int b      = n / (L * D);          // batch size (8 here)

    const dim3 grid(L / POS_PER_BLOCK);      // 2048 blocks
    const dim3 block(256);
    pe_add_kernel<<<grid, block>>>(x, out, b);
}

// round 10
// speedup vs baseline: 1.0099x; 1.0099x over previous
#include <cuda_runtime.h>
#include <math.h>

// SpatialPositionalEncoding2D: out[b,l,d] = x[b,l,d] + pe(l,d)
// h = w = 128, L = 16384, D = 256, dh = 128, b = 8.
// pe(l, d):
//   row = l / 128, col = l % 128
//   d <  128: j = d/2,        arg = row * freq[j]
//   d >= 128: j = (d-128)/2,  arg = col * freq[j]
//   freq[j] = exp(-2*j * ln(10000)/128); even d -> sin, odd d -> cos.
//
// FINAL (9-round session conclusion): pinned at the GB300 mixed read+write
// HBM streaming ceiling (~6.0 TB/s, 74-75% of 8 TB/s read spec). Probed and
// rejected: occupancy 41-84%, MLP 1-8, 320 in-flight loads/SM, L2-hot PE
// table, contiguous memcpy-shaped access, ldcg/ldcs/evict_last/stcs cache
// policies, 256-bit ld/st. All landed 36.1-37.5us kernel / 71-75% DRAM.
// Best measured config (twice: 36.45us and 36.06us kernel): one launch,
// inline trig amortized over the batch-8 images (fma pipe ~8%), all 8 loads
// in flight before stores, float4 accesses, default cache policy.

namespace {
constexpr int H  = 128;
constexpr int W  = 128;
constexpr int L  = H * W;     // 16384
constexpr int D  = 256;
constexpr int D4 = D / 4;     // 64 float4 per position
constexpr unsigned STRIDE4 = (unsigned)L * D4;   // float4 per batch image
constexpr int POS_PER_BLOCK = 4;   // 256 threads = 4 positions x 64 quads
}

__global__ void __launch_bounds__(256, 4)
pe_add_kernel(const float4* __restrict__ x, float4* __restrict__ out, int b)
{
    const int tid = threadIdx.x;
    const int lq  = tid & (D4 - 1);                 // channel-quad index 0..63
    const int l   = (blockIdx.x << 2) + (tid >> 6); // position 0..16383
    const int d0  = lq << 2;                        // first channel of this quad

    const int row = l >> 7;        // l / 128
    const int col = l & (W - 1);   // l % 128

    // All 4 channels in this quad live in one half (split at d=128).
    const bool rhalf = (d0 < 128);
    const float pos  = rhalf ? (float)row : (float)col;
    const int   j0   = rhalf ? (d0 >> 1) : ((d0 - 128) >> 1);

    // freq[j] = exp(j * (-2*ln(10000)/128))
    const float KF = -0.14391156831212787f;  // -2*ln(10000)/128
    const float f0 = expf((float)j0 * KF);
    const float f1 = expf((float)(j0 + 1) * KF);

    float s0, c0, s1, c1;
    sincosf(pos * f0, &s0, &c0);
    sincosf(pos * f1, &s1, &c1);
    const float4 pe = make_float4(s0, c0, s1, c1);

    // 32-bit addressing: max offset 128 MiB of float4 < 2^31.
    const unsigned base = (unsigned)l * D4 + (unsigned)lq;

    if (b == 8) {
        // All 8 loads in flight before any store (MLP=8 per thread).
        float4 v[8];
        #pragma unroll
        for (int bi = 0; bi < 8; bi++)
            v[bi] = x[base + bi * STRIDE4];
        #pragma unroll
        for (int bi = 0; bi < 8; bi++) {
            v[bi].x += pe.x; v[bi].y += pe.y; v[bi].z += pe.z; v[bi].w += pe.w;
            out[base + bi * STRIDE4] = v[bi];
        }
    } else {
        for (int bi = 0; bi < b; bi++) {
            float4 v = x[base + bi * STRIDE4];
            v.x += pe.x; v.y += pe.y; v.z += pe.z; v.w += pe.w;
            out[base + bi * STRIDE4] = v;
        }
    }
}

extern "C" void kernel_launch(void* const* d_in, const int* in_sizes, int n_in,
                              void* d_out, int out_size)
{
    const float4* x  = (const float4*)d_in[0];
    float4* out      = (float4*)d_out;
    const int n      = in_sizes[0];          // total elements of x
    const int b      = n / (L * D);          // batch size (8 here)

    const dim3 grid(L / POS_PER_BLOCK);      // 4096 blocks
    const dim3 block(256);
    pe_add_kernel<<<grid, block>>>(x, out, b);
}